// round 7
// baseline (speedup 1.0000x reference)
#include <cuda_runtime.h>
#include <cuda_bf16.h>
#include <cstdint>

#define D_MODEL 1024
#define D_INNER 2048
#define D_STATE 16
#define DT_RANK 64
#define D_CONV  4
#define N_LAYER 4
#define VOCAB   32000
#define Bb      2
#define Ll      1024
#define ROWS    (Bb * Ll)   // 2048
#define XP_N    96          // DT_RANK + 2*D_STATE
#define XP_NPAD 128

// ---------------- scratch (static device arrays; no allocs) ----------------
__device__ float g_x  [ROWS * D_MODEL];       // residual stream
__device__ float g_xz [ROWS * 2 * D_INNER];   // in_proj output (u|z)
__device__ float g_u  [ROWS * D_INNER];       // conv+silu output (fp32)
__device__ float g_dbl[ROWS * XP_N];          // x_proj output (fp32, scan)
__device__ float g_dt [ROWS * D_INNER];       // softplus(dt)

// bf16 hi/lo split scratch
__device__ __nv_bfloat16 g_win_h [N_LAYER * 2 * D_INNER * D_MODEL];
__device__ __nv_bfloat16 g_win_l [N_LAYER * 2 * D_INNER * D_MODEL];
__device__ __nv_bfloat16 g_wout_h[N_LAYER * D_MODEL * D_INNER];
__device__ __nv_bfloat16 g_wout_l[N_LAYER * D_MODEL * D_INNER];
__device__ __nv_bfloat16 g_wxp_h [N_LAYER * XP_NPAD * D_INNER];  // rows 96..127 zero
__device__ __nv_bfloat16 g_wxp_l [N_LAYER * XP_NPAD * D_INNER];
__device__ __nv_bfloat16 g_wdt_h [N_LAYER * D_INNER * DT_RANK];  // [2048,64]
__device__ __nv_bfloat16 g_wdt_l [N_LAYER * D_INNER * DT_RANK];
__device__ __nv_bfloat16 g_whd_h [VOCAB * D_MODEL];
__device__ __nv_bfloat16 g_whd_l [VOCAB * D_MODEL];
__device__ __nv_bfloat16 g_ah  [ROWS * D_INNER];    // activation hi
__device__ __nv_bfloat16 g_al  [ROWS * D_INNER];    // activation lo
__device__ __nv_bfloat16 g_dblh[ROWS * XP_N];       // dbl hi (dt GEMM A)
__device__ __nv_bfloat16 g_dbll[ROWS * XP_N];       // dbl lo

// ---------------- PTX helpers ----------------
__device__ __forceinline__ uint32_t smem_u32(const void* p) {
    uint32_t a;
    asm("{ .reg .u64 t; cvta.to.shared.u64 t, %1; cvt.u32.u64 %0, t; }"
        : "=r"(a) : "l"(p));
    return a;
}
__device__ __forceinline__ void cp16(uint32_t s, const void* g) {
    asm volatile("cp.async.cg.shared.global [%0], [%1], 16;\n"
                 :: "r"(s), "l"(__cvta_generic_to_global(g)) : "memory");
}
__device__ __forceinline__ void ldm_x4(uint32_t a, uint32_t* r) {
    asm volatile("ldmatrix.sync.aligned.m8n8.x4.shared.b16 {%0,%1,%2,%3}, [%4];"
                 : "=r"(r[0]), "=r"(r[1]), "=r"(r[2]), "=r"(r[3]) : "r"(a));
}
__device__ __forceinline__ void mma16816(float* c, const uint32_t* a, const uint32_t* b) {
    asm volatile(
        "mma.sync.aligned.m16n8k16.row.col.f32.bf16.bf16.f32 "
        "{%0,%1,%2,%3},{%4,%5,%6,%7},{%8,%9},{%0,%1,%2,%3};"
        : "+f"(c[0]), "+f"(c[1]), "+f"(c[2]), "+f"(c[3])
        : "r"(a[0]), "r"(a[1]), "r"(a[2]), "r"(a[3]), "r"(b[0]), "r"(b[1]));
}
__device__ __forceinline__ void split1(float v, __nv_bfloat16* oh, __nv_bfloat16* ol) {
    __nv_bfloat16 h = __float2bfloat16(v);
    *oh = h;
    *ol = __float2bfloat16(v - __bfloat162float(h));
}

// ---------------- HMMA GEMM: C[M,N] = A[M,K] * Bt[N,K]^T (+epilogue) -------
// bf16 hi/lo split operands, 3-term product (AhBh+AhBl+AlBh) ~ fp32 accuracy.
// EPI 0: plain          EPI 1: softplus(v + aux[col])
// EPI 2: v + aux[row*ldc+col]   EPI 3: plain + split-store to Ch/Cl (ldc)
// BN = 128 (NSTG=3, warp 64x32) or 256 (NSTG=2, warp 64x64).
#define GEMM_SMEM 122880

template <int EPI, int BN>
__global__ __launch_bounds__(256)
void hmma_gemm_kernel(int M, int N, int K, int lda, int ldb,
                      const __nv_bfloat16* __restrict__ Ah,
                      const __nv_bfloat16* __restrict__ Al,
                      const __nv_bfloat16* __restrict__ Bh,
                      const __nv_bfloat16* __restrict__ Bl,
                      float* __restrict__ C, int ldc,
                      const float* __restrict__ aux,
                      __nv_bfloat16* __restrict__ Ch,
                      __nv_bfloat16* __restrict__ Cl) {
    constexpr int NSTG  = (BN == 128) ? 3 : 2;
    constexpr int BUFA  = 128 * 80;
    constexpr int BUFBB = BN * 80;
    constexpr int STAGE = 2 * BUFA + 2 * BUFBB;
    constexpr int NT    = BN / 32;          // n-tiles per warp

    extern __shared__ char smem[];
    const uint32_t sb = smem_u32(smem);
    const int tid  = threadIdx.x;
    const int lane = tid & 31;
    const int w    = tid >> 5;
    const int wm   = w >> 2;
    const int wn   = w & 3;
    const int rowA = blockIdx.x * 128;
    const int colC = blockIdx.y * BN;

    const int r0 = tid >> 2, c0 = tid & 3;
    const int kiters = K >> 5;

    auto load_stage = [&](int it) {
        const uint32_t st = sb + (uint32_t)(it % NSTG) * STAGE;
        const int k0 = it << 5;
        #pragma unroll
        for (int t = 0; t < 2; t++) {
            int r = r0 + t * 64;
            uint32_t so = (uint32_t)r * 80 + c0 * 16;
            cp16(st +        so, Ah + (size_t)(rowA + r) * lda + k0 + c0 * 8);
            cp16(st + BUFA + so, Al + (size_t)(rowA + r) * lda + k0 + c0 * 8);
        }
        #pragma unroll
        for (int t = 0; t < BN / 64; t++) {
            int r = r0 + t * 64;
            uint32_t so = (uint32_t)r * 80 + c0 * 16;
            cp16(st + 2 * BUFA +         so, Bh + (size_t)(colC + r) * ldb + k0 + c0 * 8);
            cp16(st + 2 * BUFA + BUFBB + so, Bl + (size_t)(colC + r) * ldb + k0 + c0 * 8);
        }
        asm volatile("cp.async.commit_group;" ::: "memory");
    };

    float acc[4][NT][4];
    #pragma unroll
    for (int m = 0; m < 4; m++)
        #pragma unroll
        for (int n = 0; n < NT; n++)
            #pragma unroll
            for (int e = 0; e < 4; e++) acc[m][n][e] = 0.f;

    load_stage(0);
    if (kiters > 1) load_stage(1);

    const int ar  = lane & 15;
    const int ac8 = (lane >> 4) << 3;

    for (int i = 0; i < kiters; i++) {
        if (i + 1 < kiters) asm volatile("cp.async.wait_group 1;" ::: "memory");
        else                asm volatile("cp.async.wait_group 0;" ::: "memory");
        __syncthreads();
        if (NSTG == 3 && i + 2 < kiters) load_stage(i + 2);

        const uint32_t st = sb + (uint32_t)(i % NSTG) * STAGE;
        #pragma unroll
        for (int kk = 0; kk < 32; kk += 16) {
            uint32_t ah[4][4], al[4][4], bh[NT][2], bl[NT][2];
            #pragma unroll
            for (int m = 0; m < 4; m++) {
                uint32_t adr = st + (uint32_t)(wm * 64 + m * 16 + ar) * 80
                                  + (kk + ac8) * 2;
                ldm_x4(adr, ah[m]);
                ldm_x4(adr + BUFA, al[m]);
            }
            #pragma unroll
            for (int n2 = 0; n2 < NT / 2; n2++) {
                uint32_t adr = st + 2 * BUFA
                                  + (uint32_t)(wn * (BN / 4) + n2 * 16 + ar) * 80
                                  + (kk + ac8) * 2;
                uint32_t r4[4];
                ldm_x4(adr, r4);
                bh[2*n2][0] = r4[0]; bh[2*n2+1][0] = r4[1];
                bh[2*n2][1] = r4[2]; bh[2*n2+1][1] = r4[3];
                ldm_x4(adr + BUFBB, r4);
                bl[2*n2][0] = r4[0]; bl[2*n2+1][0] = r4[1];
                bl[2*n2][1] = r4[2]; bl[2*n2+1][1] = r4[3];
            }
            // term-major: long reuse distance on each accumulator
            #pragma unroll
            for (int m = 0; m < 4; m++)
                #pragma unroll
                for (int n = 0; n < NT; n++)
                    mma16816(acc[m][n], ah[m], bh[n]);
            #pragma unroll
            for (int m = 0; m < 4; m++)
                #pragma unroll
                for (int n = 0; n < NT; n++)
                    mma16816(acc[m][n], ah[m], bl[n]);
            #pragma unroll
            for (int m = 0; m < 4; m++)
                #pragma unroll
                for (int n = 0; n < NT; n++)
                    mma16816(acc[m][n], al[m], bh[n]);
        }
        __syncthreads();
        if (NSTG == 2 && i + 2 < kiters) load_stage(i + 2);
    }

    const int er = lane >> 2;
    const int ec = (lane & 3) * 2;
    #pragma unroll
    for (int m = 0; m < 4; m++) {
        const int grow = rowA + wm * 64 + m * 16 + er;
        #pragma unroll
        for (int n = 0; n < NT; n++) {
            const int gcol = colC + wn * (BN / 4) + n * 8 + ec;
            if (gcol >= N) continue;
            float2 v0 = make_float2(acc[m][n][0], acc[m][n][1]);
            float2 v1 = make_float2(acc[m][n][2], acc[m][n][3]);
            if (EPI == 1) {
                float b0 = aux[gcol], b1 = aux[gcol + 1];
                v0.x += b0; v0.y += b1;
                v1.x += b0; v1.y += b1;
                v0.x = (v0.x > 20.f) ? v0.x : log1pf(__expf(v0.x));
                v0.y = (v0.y > 20.f) ? v0.y : log1pf(__expf(v0.y));
                v1.x = (v1.x > 20.f) ? v1.x : log1pf(__expf(v1.x));
                v1.y = (v1.y > 20.f) ? v1.y : log1pf(__expf(v1.y));
            } else if (EPI == 2) {
                float2 a0 = *reinterpret_cast<const float2*>(
                    aux + (size_t)grow * ldc + gcol);
                float2 a1 = *reinterpret_cast<const float2*>(
                    aux + (size_t)(grow + 8) * ldc + gcol);
                v0.x += a0.x; v0.y += a0.y;
                v1.x += a1.x; v1.y += a1.y;
            }
            *reinterpret_cast<float2*>(C + (size_t)grow * ldc + gcol) = v0;
            *reinterpret_cast<float2*>(C + (size_t)(grow + 8) * ldc + gcol) = v1;
            if (EPI == 3) {
                __nv_bfloat16 h0, l0, h1, l1;
                split1(v0.x, &h0, &l0); split1(v0.y, &h1, &l1);
                *reinterpret_cast<__nv_bfloat162*>(Ch + (size_t)grow * ldc + gcol) =
                    __nv_bfloat162(h0, h1);
                *reinterpret_cast<__nv_bfloat162*>(Cl + (size_t)grow * ldc + gcol) =
                    __nv_bfloat162(l0, l1);
                split1(v1.x, &h0, &l0); split1(v1.y, &h1, &l1);
                *reinterpret_cast<__nv_bfloat162*>(Ch + (size_t)(grow + 8) * ldc + gcol) =
                    __nv_bfloat162(h0, h1);
                *reinterpret_cast<__nv_bfloat162*>(Cl + (size_t)(grow + 8) * ldc + gcol) =
                    __nv_bfloat162(l0, l1);
            }
        }
    }
}

// ---------------- transpose + bf16 split: in[R,C] -> out hi/lo [C,R] -------
__global__ void tsplit_kernel(const float* __restrict__ in,
                              __nv_bfloat16* __restrict__ oh,
                              __nv_bfloat16* __restrict__ ol, int R, int Ccols) {
    __shared__ float t[32][33];
    int rb = blockIdx.x * 32, cb = blockIdx.y * 32;
    int x = threadIdx.x, y = threadIdx.y;  // (32,8)
    #pragma unroll
    for (int j = 0; j < 4; j++)
        t[y + 8 * j][x] = in[(size_t)(rb + y + 8 * j) * Ccols + cb + x];
    __syncthreads();
    #pragma unroll
    for (int j = 0; j < 4; j++) {
        float v = t[x][y + 8 * j];
        size_t o = (size_t)(cb + y + 8 * j) * R + rb + x;
        split1(v, oh + o, ol + o);
    }
}

// ---------------- embedding gather ----------------
__global__ void embed_kernel(const int* __restrict__ tokens,
                             const float* __restrict__ emb) {
    int idx = blockIdx.x * blockDim.x + threadIdx.x;
    if (idx >= ROWS * D_MODEL) return;
    int row = idx / D_MODEL;
    int c   = idx % D_MODEL;
    g_x[idx] = emb[tokens[row] * D_MODEL + c];
}

// ---------------- rmsnorm -> bf16 hi/lo ----------------
__global__ void rmsnorm_kernel(const float* __restrict__ in,
                               const float* __restrict__ w,
                               __nv_bfloat16* __restrict__ oh,
                               __nv_bfloat16* __restrict__ ol) {
    __shared__ float red[8];
    int row = blockIdx.x;
    const float4* x4 = reinterpret_cast<const float4*>(in + (size_t)row * D_MODEL);
    float4 v = x4[threadIdx.x];
    float s = v.x * v.x + v.y * v.y + v.z * v.z + v.w * v.w;
    #pragma unroll
    for (int o = 16; o > 0; o >>= 1) s += __shfl_xor_sync(0xffffffffu, s, o);
    if ((threadIdx.x & 31) == 0) red[threadIdx.x >> 5] = s;
    __syncthreads();
    if (threadIdx.x < 8) {
        float t = red[threadIdx.x];
        #pragma unroll
        for (int o = 4; o > 0; o >>= 1) t += __shfl_xor_sync(0xffu, t, o);
        if (threadIdx.x == 0) red[0] = t;
    }
    __syncthreads();
    float rs = rsqrtf(red[0] * (1.0f / D_MODEL) + 1e-5f);
    const float4* w4 = reinterpret_cast<const float4*>(w);
    float4 wv = w4[threadIdx.x];
    size_t base = (size_t)row * D_MODEL + threadIdx.x * 4;
    split1(v.x * rs * wv.x, oh + base + 0, ol + base + 0);
    split1(v.y * rs * wv.y, oh + base + 1, ol + base + 1);
    split1(v.z * rs * wv.z, oh + base + 2, ol + base + 2);
    split1(v.w * rs * wv.w, oh + base + 3, ol + base + 3);
}

// ---------------- depthwise causal conv1d + silu ----------------
__global__ void conv_silu_kernel(const float* __restrict__ conv_w,
                                 const float* __restrict__ conv_b) {
    int idx = blockIdx.x * blockDim.x + threadIdx.x;
    if (idx >= ROWS * D_INNER) return;
    int d = idx % D_INNER;
    int row = idx / D_INNER;
    int l = row % Ll;
    int rowbase = row - l;
    float acc = conv_b[d];
    #pragma unroll
    for (int k = 0; k < D_CONV; k++) {
        int ll = l - (D_CONV - 1) + k;
        if (ll >= 0)
            acc = fmaf(conv_w[d * D_CONV + k],
                       g_xz[(size_t)(rowbase + ll) * (2 * D_INNER) + d], acc);
    }
    float s = acc / (1.f + __expf(-acc));
    g_u[idx] = s;
    split1(s, g_ah + idx, g_al + idx);
}

// ---------------- selective scan (writes y hi/lo) ----------------
__global__ void scan_kernel(const float* __restrict__ A_log,
                            const float* __restrict__ Dp) {
    int warp = (blockIdx.x * blockDim.x + threadIdx.x) >> 5;
    int lane = threadIdx.x & 31;
    int n = lane & 15;
    int ch = warp * 2 + (lane >> 4);
    if (ch >= Bb * D_INNER) return;
    int b = ch / D_INNER;
    int d = ch % D_INNER;

    float An = -__expf(A_log[d * D_STATE + n]);
    float Dd = Dp[d];
    float h = 0.f;

    int base = b * Ll;
    for (int l = 0; l < Ll; l++) {
        int r = base + l;
        float dt_v = g_dt[(size_t)r * D_INNER + d];
        float u_v  = g_u [(size_t)r * D_INNER + d];
        float Bn = g_dbl[r * XP_N + DT_RANK + n];
        float Cn = g_dbl[r * XP_N + DT_RANK + D_STATE + n];
        h = fmaf(__expf(dt_v * An), h, dt_v * Bn * u_v);
        float p = h * Cn;
        #pragma unroll
        for (int o = 8; o > 0; o >>= 1)
            p += __shfl_xor_sync(0xffffffffu, p, o);
        if (n == 0) {
            float zv = g_xz[(size_t)r * (2 * D_INNER) + D_INNER + d];
            float yv = (p + u_v * Dd) * (zv / (1.f + __expf(-zv)));
            size_t o = (size_t)r * D_INNER + d;
            split1(yv, g_ah + o, g_al + o);
        }
    }
}

// ---------------- launch ----------------
extern "C" void kernel_launch(void* const* d_in, const int* in_sizes, int n_in,
                              void* d_out, int out_size) {
    const int*   tokens    = (const int*)  d_in[0];
    const float* embedding = (const float*)d_in[1];
    const float* norm_w    = (const float*)d_in[2];
    const float* in_proj   = (const float*)d_in[3];
    const float* conv_w    = (const float*)d_in[4];
    const float* conv_b    = (const float*)d_in[5];
    const float* x_proj    = (const float*)d_in[6];
    const float* dt_w      = (const float*)d_in[7];
    const float* dt_b      = (const float*)d_in[8];
    const float* A_log     = (const float*)d_in[9];
    const float* Dp        = (const float*)d_in[10];
    const float* out_proj  = (const float*)d_in[11];
    const float* fnorm_w   = (const float*)d_in[12];
    const float* head_w    = (const float*)d_in[13];
    float* out = (float*)d_out;

    float *px, *pxz, *pu, *pdbl, *pdt;
    cudaGetSymbolAddress((void**)&px,  g_x);
    cudaGetSymbolAddress((void**)&pxz, g_xz);
    cudaGetSymbolAddress((void**)&pu,  g_u);
    cudaGetSymbolAddress((void**)&pdbl,g_dbl);
    cudaGetSymbolAddress((void**)&pdt, g_dt);

    __nv_bfloat16 *pwin_h, *pwin_l, *pwout_h, *pwout_l, *pwxp_h, *pwxp_l,
                  *pwdt_h, *pwdt_l, *phd_h, *phd_l, *pah, *pal, *pdblh, *pdbll;
    cudaGetSymbolAddress((void**)&pwin_h,  g_win_h);
    cudaGetSymbolAddress((void**)&pwin_l,  g_win_l);
    cudaGetSymbolAddress((void**)&pwout_h, g_wout_h);
    cudaGetSymbolAddress((void**)&pwout_l, g_wout_l);
    cudaGetSymbolAddress((void**)&pwxp_h,  g_wxp_h);
    cudaGetSymbolAddress((void**)&pwxp_l,  g_wxp_l);
    cudaGetSymbolAddress((void**)&pwdt_h,  g_wdt_h);
    cudaGetSymbolAddress((void**)&pwdt_l,  g_wdt_l);
    cudaGetSymbolAddress((void**)&phd_h,   g_whd_h);
    cudaGetSymbolAddress((void**)&phd_l,   g_whd_l);
    cudaGetSymbolAddress((void**)&pah,     g_ah);
    cudaGetSymbolAddress((void**)&pal,     g_al);
    cudaGetSymbolAddress((void**)&pdblh,   g_dblh);
    cudaGetSymbolAddress((void**)&pdbll,   g_dbll);

    cudaFuncSetAttribute(hmma_gemm_kernel<0, 256>,
                         cudaFuncAttributeMaxDynamicSharedMemorySize, GEMM_SMEM);
    cudaFuncSetAttribute(hmma_gemm_kernel<3, 128>,
                         cudaFuncAttributeMaxDynamicSharedMemorySize, GEMM_SMEM);
    cudaFuncSetAttribute(hmma_gemm_kernel<1, 128>,
                         cudaFuncAttributeMaxDynamicSharedMemorySize, GEMM_SMEM);
    cudaFuncSetAttribute(hmma_gemm_kernel<2, 128>,
                         cudaFuncAttributeMaxDynamicSharedMemorySize, GEMM_SMEM);

    dim3 tsB(32, 8);

    // #1
    embed_kernel<<<(ROWS * D_MODEL + 255) / 256, 256>>>(tokens, embedding);

    for (int i = 0; i < N_LAYER; i++) {
        const float* w_norm = norm_w   + (size_t)i * D_MODEL;
        const float* w_cw   = conv_w   + (size_t)i * D_INNER * D_CONV;
        const float* w_cb   = conv_b   + (size_t)i * D_INNER;
        const float* w_dtb  = dt_b     + (size_t)i * D_INNER;
        const float* w_Alog = A_log    + (size_t)i * D_INNER * D_STATE;
        const float* w_D    = Dp       + (size_t)i * D_INNER;

        // #2 (layer 0)
        tsplit_kernel<<<dim3(D_MODEL / 32, (2 * D_INNER) / 32), tsB>>>(
            in_proj + (size_t)i * D_MODEL * 2 * D_INNER,
            pwin_h + (size_t)i * 2 * D_INNER * D_MODEL,
            pwin_l + (size_t)i * 2 * D_INNER * D_MODEL, D_MODEL, 2 * D_INNER);
        // #3 (layer 0)
        rmsnorm_kernel<<<ROWS, 256>>>(px, w_norm, pah, pal);
        // #4 (layer 0)  <-- ncu capture target
        hmma_gemm_kernel<0, 256><<<dim3(ROWS / 128, (2 * D_INNER) / 256), 256, GEMM_SMEM>>>(
            ROWS, 2 * D_INNER, D_MODEL, D_MODEL, D_MODEL, pah, pal,
            pwin_h + (size_t)i * 2 * D_INNER * D_MODEL,
            pwin_l + (size_t)i * 2 * D_INNER * D_MODEL,
            pxz, 2 * D_INNER, nullptr, nullptr, nullptr);

        conv_silu_kernel<<<(ROWS * D_INNER + 255) / 256, 256>>>(w_cw, w_cb);

        // x_proj: dbl = u @ x_proj  (fp32 + hi/lo split out)
        tsplit_kernel<<<dim3(D_INNER / 32, XP_N / 32), tsB>>>(
            x_proj + (size_t)i * D_INNER * XP_N,
            pwxp_h + (size_t)i * XP_NPAD * D_INNER,
            pwxp_l + (size_t)i * XP_NPAD * D_INNER, D_INNER, XP_N);
        hmma_gemm_kernel<3, 128><<<dim3(ROWS / 128, 1), 256, GEMM_SMEM>>>(
            ROWS, XP_N, D_INNER, D_INNER, D_INNER, pah, pal,
            pwxp_h + (size_t)i * XP_NPAD * D_INNER,
            pwxp_l + (size_t)i * XP_NPAD * D_INNER,
            pdbl, XP_N, nullptr, pdblh, pdbll);

        // dt = softplus(dbl[:, :64] @ dt_w + dt_b)  on HMMA (K=64)
        tsplit_kernel<<<dim3(DT_RANK / 32, D_INNER / 32), tsB>>>(
            dt_w + (size_t)i * DT_RANK * D_INNER,
            pwdt_h + (size_t)i * D_INNER * DT_RANK,
            pwdt_l + (size_t)i * D_INNER * DT_RANK, DT_RANK, D_INNER);
        hmma_gemm_kernel<1, 128><<<dim3(ROWS / 128, D_INNER / 128), 256, GEMM_SMEM>>>(
            ROWS, D_INNER, DT_RANK, XP_N, DT_RANK, pdblh, pdbll,
            pwdt_h + (size_t)i * D_INNER * DT_RANK,
            pwdt_l + (size_t)i * D_INNER * DT_RANK,
            pdt, D_INNER, w_dtb, nullptr, nullptr);

        scan_kernel<<<256, 256>>>(w_Alog, w_D);

        // x = y @ out_proj + x
        tsplit_kernel<<<dim3(D_INNER / 32, D_MODEL / 32), tsB>>>(
            out_proj + (size_t)i * D_INNER * D_MODEL,
            pwout_h + (size_t)i * D_MODEL * D_INNER,
            pwout_l + (size_t)i * D_MODEL * D_INNER, D_INNER, D_MODEL);
        hmma_gemm_kernel<2, 128><<<dim3(ROWS / 128, D_MODEL / 128), 256, GEMM_SMEM>>>(
            ROWS, D_MODEL, D_INNER, D_INNER, D_INNER, pah, pal,
            pwout_h + (size_t)i * D_MODEL * D_INNER,
            pwout_l + (size_t)i * D_MODEL * D_INNER,
            px, D_MODEL, px, nullptr, nullptr);
    }

    rmsnorm_kernel<<<ROWS, 256>>>(px, fnorm_w, pah, pal);

    tsplit_kernel<<<dim3(D_MODEL / 32, VOCAB / 32), tsB>>>(
        head_w, phd_h, phd_l, D_MODEL, VOCAB);

    // logits = xn @ head_w
    hmma_gemm_kernel<0, 256><<<dim3(ROWS / 128, VOCAB / 256), 256, GEMM_SMEM>>>(
        ROWS, VOCAB, D_MODEL, D_MODEL, D_MODEL, pah, pal, phd_h, phd_l,
        out, VOCAB, nullptr, nullptr, nullptr);
}

// round 9
// speedup vs baseline: 1.0565x; 1.0565x over previous
#include <cuda_runtime.h>
#include <cuda_bf16.h>
#include <cstdint>

#define D_MODEL 1024
#define D_INNER 2048
#define D_STATE 16
#define DT_RANK 64
#define D_CONV  4
#define N_LAYER 4
#define VOCAB   32000
#define Bb      2
#define Ll      1024
#define ROWS    (Bb * Ll)   // 2048
#define XP_N    96
#define XP_NPAD 128

// ---------------- scratch ----------------
__device__ float g_x  [ROWS * D_MODEL];
__device__ float g_xz [ROWS * 2 * D_INNER];
__device__ float g_u  [ROWS * D_INNER];
__device__ float g_dbl[ROWS * XP_N];
__device__ float g_dt [ROWS * D_INNER];

__device__ __nv_bfloat16 g_win_h [N_LAYER * 2 * D_INNER * D_MODEL];
__device__ __nv_bfloat16 g_win_l [N_LAYER * 2 * D_INNER * D_MODEL];
__device__ __nv_bfloat16 g_wout_h[N_LAYER * D_MODEL * D_INNER];
__device__ __nv_bfloat16 g_wout_l[N_LAYER * D_MODEL * D_INNER];
__device__ __nv_bfloat16 g_wxp_h [N_LAYER * XP_NPAD * D_INNER];  // rows 96..127 zero
__device__ __nv_bfloat16 g_wxp_l [N_LAYER * XP_NPAD * D_INNER];
__device__ __nv_bfloat16 g_wdt_h [N_LAYER * D_INNER * DT_RANK];
__device__ __nv_bfloat16 g_wdt_l [N_LAYER * D_INNER * DT_RANK];
__device__ __nv_bfloat16 g_whd_h [VOCAB * D_MODEL];
__device__ __nv_bfloat16 g_whd_l [VOCAB * D_MODEL];
__device__ __nv_bfloat16 g_ah  [ROWS * D_INNER];
__device__ __nv_bfloat16 g_al  [ROWS * D_INNER];
__device__ __nv_bfloat16 g_dblh[ROWS * XP_N];
__device__ __nv_bfloat16 g_dbll[ROWS * XP_N];

// ---------------- PTX helpers ----------------
__device__ __forceinline__ uint32_t smem_u32(const void* p) {
    uint32_t a;
    asm("{ .reg .u64 t; cvta.to.shared.u64 t, %1; cvt.u32.u64 %0, t; }"
        : "=r"(a) : "l"(p));
    return a;
}
__device__ __forceinline__ void cp16(uint32_t s, const void* g) {
    asm volatile("cp.async.cg.shared.global [%0], [%1], 16;\n"
                 :: "r"(s), "l"(__cvta_generic_to_global(g)) : "memory");
}
__device__ __forceinline__ void ldm_x4(uint32_t a, uint32_t* r) {
    asm volatile("ldmatrix.sync.aligned.m8n8.x4.shared.b16 {%0,%1,%2,%3}, [%4];"
                 : "=r"(r[0]), "=r"(r[1]), "=r"(r[2]), "=r"(r[3]) : "r"(a));
}
__device__ __forceinline__ void mma16816(float* c, const uint32_t* a, const uint32_t* b) {
    asm volatile(
        "mma.sync.aligned.m16n8k16.row.col.f32.bf16.bf16.f32 "
        "{%0,%1,%2,%3},{%4,%5,%6,%7},{%8,%9},{%0,%1,%2,%3};"
        : "+f"(c[0]), "+f"(c[1]), "+f"(c[2]), "+f"(c[3])
        : "r"(a[0]), "r"(a[1]), "r"(a[2]), "r"(a[3]), "r"(b[0]), "r"(b[1]));
}
__device__ __forceinline__ void split1(float v, __nv_bfloat16* oh, __nv_bfloat16* ol) {
    __nv_bfloat16 h = __float2bfloat16(v);
    *oh = h;
    *ol = __float2bfloat16(v - __bfloat162float(h));
}

// swizzled 16B-slot offset within a 64B-row buffer: row r, chunk c (0..3)
__device__ __forceinline__ uint32_t sw_off(int r, int c) {
    return (uint32_t)r * 64u + (uint32_t)((c ^ ((r >> 1) & 3)) << 4);
}

// ---------------- HMMA GEMM: C[M,N] = A[M,K] * Bt[N,K]^T (+epilogue) -------
// bf16 hi/lo split operands, 3-term product. CTA 128x128, 128 threads (2x2
// warps, 64x64 warp tile), BK=32, 3-stage cp.async, XOR-swizzled smem.
// 98304 B smem -> 2 CTAs/SM.  EPI 0: plain  1: softplus(+bias[col])
// 2: +aux[row*ldc+col]  3: plain + split-store Ch/Cl
#define BUFS   8192                   // one operand buffer (128 rows x 64 B)
#define STAGE  (4 * BUFS)             // Ah,Al,Bh,Bl
#define NSTG   3
#define GEMM_SMEM (NSTG * STAGE)      // 98304

template <int EPI>
__global__ __launch_bounds__(128)
void hmma_gemm_kernel(int M, int N, int K, int lda, int ldb,
                      const __nv_bfloat16* __restrict__ Ah,
                      const __nv_bfloat16* __restrict__ Al,
                      const __nv_bfloat16* __restrict__ Bh,
                      const __nv_bfloat16* __restrict__ Bl,
                      float* __restrict__ C, int ldc,
                      const float* __restrict__ aux,
                      __nv_bfloat16* __restrict__ Ch,
                      __nv_bfloat16* __restrict__ Cl) {
    extern __shared__ char smem[];
    const uint32_t sb = smem_u32(smem);
    const int tid  = threadIdx.x;
    const int lane = tid & 31;
    const int w    = tid >> 5;
    const int wm   = w >> 1;          // 0..1
    const int wn   = w & 1;           // 0..1
    const int rowA = blockIdx.x * 128;
    const int colC = blockIdx.y * 128;

    const int kiters = K >> 5;

    auto load_stage = [&](int it) {
        const uint32_t st = sb + (uint32_t)(it % NSTG) * STAGE;
        const int k0 = it << 5;
        #pragma unroll
        for (int t = 0; t < 4; t++) {
            int idx = tid + t * 128;
            int r = idx >> 2, c = idx & 3;
            uint32_t so = sw_off(r, c);
            const size_t ga = (size_t)(rowA + r) * lda + k0 + c * 8;
            const size_t gb = (size_t)(colC + r) * ldb + k0 + c * 8;
            cp16(st +            so, Ah + ga);
            cp16(st + BUFS     + so, Al + ga);
            cp16(st + 2 * BUFS + so, Bh + gb);
            cp16(st + 3 * BUFS + so, Bl + gb);
        }
        asm volatile("cp.async.commit_group;" ::: "memory");
    };

    float acc[4][8][4];
    #pragma unroll
    for (int m = 0; m < 4; m++)
        #pragma unroll
        for (int n = 0; n < 8; n++)
            #pragma unroll
            for (int e = 0; e < 4; e++) acc[m][n][e] = 0.f;

    load_stage(0);
    if (kiters > 1) load_stage(1);

    const int lr  = lane & 15;        // row within 16-row group
    const int lc  = lane >> 4;        // 16B-column half (0/1)

    for (int i = 0; i < kiters; i++) {
        if (i + 1 < kiters) asm volatile("cp.async.wait_group 1;" ::: "memory");
        else                asm volatile("cp.async.wait_group 0;" ::: "memory");
        __syncthreads();
        if (i + 2 < kiters) load_stage(i + 2);

        const uint32_t st = sb + (uint32_t)(i % NSTG) * STAGE;
        #pragma unroll
        for (int kk = 0; kk < 2; kk++) {          // two k16 halves
            const int cbase = kk * 2 + lc;        // 16B chunk index 0..3
            uint32_t ah[4][4], al[4][4], bh[8][2], bl[8][2];
            #pragma unroll
            for (int m = 0; m < 4; m++) {
                int r = wm * 64 + m * 16 + lr;
                uint32_t adr = st + sw_off(r, cbase);
                ldm_x4(adr, ah[m]);
                ldm_x4(adr + BUFS, al[m]);
            }
            #pragma unroll
            for (int n2 = 0; n2 < 4; n2++) {
                int r = wn * 64 + n2 * 16 + lr;
                uint32_t adr = st + 2 * BUFS + sw_off(r, cbase);
                uint32_t r4[4];
                ldm_x4(adr, r4);
                bh[2*n2][0] = r4[0]; bh[2*n2+1][0] = r4[1];
                bh[2*n2][1] = r4[2]; bh[2*n2+1][1] = r4[3];
                ldm_x4(adr + BUFS, r4);
                bl[2*n2][0] = r4[0]; bl[2*n2+1][0] = r4[1];
                bl[2*n2][1] = r4[2]; bl[2*n2+1][1] = r4[3];
            }
            #pragma unroll
            for (int m = 0; m < 4; m++)
                #pragma unroll
                for (int n = 0; n < 8; n++)
                    mma16816(acc[m][n], ah[m], bh[n]);
            #pragma unroll
            for (int m = 0; m < 4; m++)
                #pragma unroll
                for (int n = 0; n < 8; n++)
                    mma16816(acc[m][n], ah[m], bl[n]);
            #pragma unroll
            for (int m = 0; m < 4; m++)
                #pragma unroll
                for (int n = 0; n < 8; n++)
                    mma16816(acc[m][n], al[m], bh[n]);
        }
        __syncthreads();
    }

    const int er = lane >> 2;
    const int ec = (lane & 3) * 2;
    #pragma unroll
    for (int m = 0; m < 4; m++) {
        const int grow = rowA + wm * 64 + m * 16 + er;
        #pragma unroll
        for (int n = 0; n < 8; n++) {
            const int gcol = colC + wn * 64 + n * 8 + ec;
            if (gcol >= N) continue;
            float2 v0 = make_float2(acc[m][n][0], acc[m][n][1]);
            float2 v1 = make_float2(acc[m][n][2], acc[m][n][3]);
            if (EPI == 1) {
                float b0 = aux[gcol], b1 = aux[gcol + 1];
                v0.x += b0; v0.y += b1;
                v1.x += b0; v1.y += b1;
                v0.x = (v0.x > 20.f) ? v0.x : log1pf(__expf(v0.x));
                v0.y = (v0.y > 20.f) ? v0.y : log1pf(__expf(v0.y));
                v1.x = (v1.x > 20.f) ? v1.x : log1pf(__expf(v1.x));
                v1.y = (v1.y > 20.f) ? v1.y : log1pf(__expf(v1.y));
            } else if (EPI == 2) {
                float2 a0 = *reinterpret_cast<const float2*>(
                    aux + (size_t)grow * ldc + gcol);
                float2 a1 = *reinterpret_cast<const float2*>(
                    aux + (size_t)(grow + 8) * ldc + gcol);
                v0.x += a0.x; v0.y += a0.y;
                v1.x += a1.x; v1.y += a1.y;
            }
            *reinterpret_cast<float2*>(C + (size_t)grow * ldc + gcol) = v0;
            *reinterpret_cast<float2*>(C + (size_t)(grow + 8) * ldc + gcol) = v1;
            if (EPI == 3) {
                __nv_bfloat16 h0, l0, h1, l1;
                split1(v0.x, &h0, &l0); split1(v0.y, &h1, &l1);
                *reinterpret_cast<__nv_bfloat162*>(Ch + (size_t)grow * ldc + gcol) =
                    __nv_bfloat162(h0, h1);
                *reinterpret_cast<__nv_bfloat162*>(Cl + (size_t)grow * ldc + gcol) =
                    __nv_bfloat162(l0, l1);
                split1(v1.x, &h0, &l0); split1(v1.y, &h1, &l1);
                *reinterpret_cast<__nv_bfloat162*>(Ch + (size_t)(grow + 8) * ldc + gcol) =
                    __nv_bfloat162(h0, h1);
                *reinterpret_cast<__nv_bfloat162*>(Cl + (size_t)(grow + 8) * ldc + gcol) =
                    __nv_bfloat162(l0, l1);
            }
        }
    }
}

// ---------------- transpose + bf16 split: in[R,C] -> hi/lo [C,R] ----------
__global__ void tsplit_kernel(const float* __restrict__ in,
                              __nv_bfloat16* __restrict__ oh,
                              __nv_bfloat16* __restrict__ ol, int R, int Ccols) {
    __shared__ float t[32][33];
    int rb = blockIdx.x * 32, cb = blockIdx.y * 32;
    int x = threadIdx.x, y = threadIdx.y;
    #pragma unroll
    for (int j = 0; j < 4; j++)
        t[y + 8 * j][x] = in[(size_t)(rb + y + 8 * j) * Ccols + cb + x];
    __syncthreads();
    #pragma unroll
    for (int j = 0; j < 4; j++) {
        float v = t[x][y + 8 * j];
        size_t o = (size_t)(cb + y + 8 * j) * R + rb + x;
        split1(v, oh + o, ol + o);
    }
}

// ---------------- embedding ----------------
__global__ void embed_kernel(const int* __restrict__ tokens,
                             const float* __restrict__ emb) {
    int idx = blockIdx.x * blockDim.x + threadIdx.x;
    if (idx >= ROWS * D_MODEL) return;
    int row = idx / D_MODEL;
    int c   = idx % D_MODEL;
    g_x[idx] = emb[tokens[row] * D_MODEL + c];
}

// ---------------- rmsnorm -> bf16 hi/lo ----------------
__global__ void rmsnorm_kernel(const float* __restrict__ in,
                               const float* __restrict__ w,
                               __nv_bfloat16* __restrict__ oh,
                               __nv_bfloat16* __restrict__ ol) {
    __shared__ float red[8];
    int row = blockIdx.x;
    const float4* x4 = reinterpret_cast<const float4*>(in + (size_t)row * D_MODEL);
    float4 v = x4[threadIdx.x];
    float s = v.x * v.x + v.y * v.y + v.z * v.z + v.w * v.w;
    #pragma unroll
    for (int o = 16; o > 0; o >>= 1) s += __shfl_xor_sync(0xffffffffu, s, o);
    if ((threadIdx.x & 31) == 0) red[threadIdx.x >> 5] = s;
    __syncthreads();
    if (threadIdx.x < 8) {
        float t = red[threadIdx.x];
        #pragma unroll
        for (int o = 4; o > 0; o >>= 1) t += __shfl_xor_sync(0xffu, t, o);
        if (threadIdx.x == 0) red[0] = t;
    }
    __syncthreads();
    float rs = rsqrtf(red[0] * (1.0f / D_MODEL) + 1e-5f);
    const float4* w4 = reinterpret_cast<const float4*>(w);
    float4 wv = w4[threadIdx.x];
    size_t base = (size_t)row * D_MODEL + threadIdx.x * 4;
    split1(v.x * rs * wv.x, oh + base + 0, ol + base + 0);
    split1(v.y * rs * wv.y, oh + base + 1, ol + base + 1);
    split1(v.z * rs * wv.z, oh + base + 2, ol + base + 2);
    split1(v.w * rs * wv.w, oh + base + 3, ol + base + 3);
}

// ---------------- depthwise causal conv1d + silu ----------------
__global__ void conv_silu_kernel(const float* __restrict__ conv_w,
                                 const float* __restrict__ conv_b) {
    int idx = blockIdx.x * blockDim.x + threadIdx.x;
    if (idx >= ROWS * D_INNER) return;
    int d = idx % D_INNER;
    int row = idx / D_INNER;
    int l = row % Ll;
    int rowbase = row - l;
    float acc = conv_b[d];
    #pragma unroll
    for (int k = 0; k < D_CONV; k++) {
        int ll = l - (D_CONV - 1) + k;
        if (ll >= 0)
            acc = fmaf(conv_w[d * D_CONV + k],
                       g_xz[(size_t)(rowbase + ll) * (2 * D_INNER) + d], acc);
    }
    float s = acc / (1.f + __expf(-acc));
    g_u[idx] = s;
    split1(s, g_ah + idx, g_al + idx);
}

// ---------------- selective scan ----------------
__global__ void scan_kernel(const float* __restrict__ A_log,
                            const float* __restrict__ Dp) {
    int warp = (blockIdx.x * blockDim.x + threadIdx.x) >> 5;
    int lane = threadIdx.x & 31;
    int n = lane & 15;
    int ch = warp * 2 + (lane >> 4);
    if (ch >= Bb * D_INNER) return;
    int b = ch / D_INNER;
    int d = ch % D_INNER;

    float An = -__expf(A_log[d * D_STATE + n]);
    float Dd = Dp[d];
    float h = 0.f;

    int base = b * Ll;
    for (int l = 0; l < Ll; l++) {
        int r = base + l;
        float dt_v = g_dt[(size_t)r * D_INNER + d];
        float u_v  = g_u [(size_t)r * D_INNER + d];
        float Bn = g_dbl[r * XP_N + DT_RANK + n];
        float Cn = g_dbl[r * XP_N + DT_RANK + D_STATE + n];
        h = fmaf(__expf(dt_v * An), h, dt_v * Bn * u_v);
        float p = h * Cn;
        #pragma unroll
        for (int o = 8; o > 0; o >>= 1)
            p += __shfl_xor_sync(0xffffffffu, p, o);
        if (n == 0) {
            float zv = g_xz[(size_t)r * (2 * D_INNER) + D_INNER + d];
            float yv = (p + u_v * Dd) * (zv / (1.f + __expf(-zv)));
            size_t o = (size_t)r * D_INNER + d;
            split1(yv, g_ah + o, g_al + o);
        }
    }
}

// ---------------- launch ----------------
extern "C" void kernel_launch(void* const* d_in, const int* in_sizes, int n_in,
                              void* d_out, int out_size) {
    const int*   tokens    = (const int*)  d_in[0];
    const float* embedding = (const float*)d_in[1];
    const float* norm_w    = (const float*)d_in[2];
    const float* in_proj   = (const float*)d_in[3];
    const float* conv_w    = (const float*)d_in[4];
    const float* conv_b    = (const float*)d_in[5];
    const float* x_proj    = (const float*)d_in[6];
    const float* dt_w      = (const float*)d_in[7];
    const float* dt_b      = (const float*)d_in[8];
    const float* A_log     = (const float*)d_in[9];
    const float* Dp        = (const float*)d_in[10];
    const float* out_proj  = (const float*)d_in[11];
    const float* fnorm_w   = (const float*)d_in[12];
    const float* head_w    = (const float*)d_in[13];
    float* out = (float*)d_out;

    float *px, *pxz, *pu, *pdbl, *pdt;
    cudaGetSymbolAddress((void**)&px,  g_x);
    cudaGetSymbolAddress((void**)&pxz, g_xz);
    cudaGetSymbolAddress((void**)&pu,  g_u);
    cudaGetSymbolAddress((void**)&pdbl,g_dbl);
    cudaGetSymbolAddress((void**)&pdt, g_dt);

    __nv_bfloat16 *pwin_h, *pwin_l, *pwout_h, *pwout_l, *pwxp_h, *pwxp_l,
                  *pwdt_h, *pwdt_l, *phd_h, *phd_l, *pah, *pal, *pdblh, *pdbll;
    cudaGetSymbolAddress((void**)&pwin_h,  g_win_h);
    cudaGetSymbolAddress((void**)&pwin_l,  g_win_l);
    cudaGetSymbolAddress((void**)&pwout_h, g_wout_h);
    cudaGetSymbolAddress((void**)&pwout_l, g_wout_l);
    cudaGetSymbolAddress((void**)&pwxp_h,  g_wxp_h);
    cudaGetSymbolAddress((void**)&pwxp_l,  g_wxp_l);
    cudaGetSymbolAddress((void**)&pwdt_h,  g_wdt_h);
    cudaGetSymbolAddress((void**)&pwdt_l,  g_wdt_l);
    cudaGetSymbolAddress((void**)&phd_h,   g_whd_h);
    cudaGetSymbolAddress((void**)&phd_l,   g_whd_l);
    cudaGetSymbolAddress((void**)&pah,     g_ah);
    cudaGetSymbolAddress((void**)&pal,     g_al);
    cudaGetSymbolAddress((void**)&pdblh,   g_dblh);
    cudaGetSymbolAddress((void**)&pdbll,   g_dbll);

    cudaFuncSetAttribute(hmma_gemm_kernel<0>,
                         cudaFuncAttributeMaxDynamicSharedMemorySize, GEMM_SMEM);
    cudaFuncSetAttribute(hmma_gemm_kernel<1>,
                         cudaFuncAttributeMaxDynamicSharedMemorySize, GEMM_SMEM);
    cudaFuncSetAttribute(hmma_gemm_kernel<2>,
                         cudaFuncAttributeMaxDynamicSharedMemorySize, GEMM_SMEM);
    cudaFuncSetAttribute(hmma_gemm_kernel<3>,
                         cudaFuncAttributeMaxDynamicSharedMemorySize, GEMM_SMEM);

    dim3 tsB(32, 8);

    // #1
    embed_kernel<<<(ROWS * D_MODEL + 255) / 256, 256>>>(tokens, embedding);

    for (int i = 0; i < N_LAYER; i++) {
        const float* w_norm = norm_w + (size_t)i * D_MODEL;
        const float* w_cw   = conv_w + (size_t)i * D_INNER * D_CONV;
        const float* w_cb   = conv_b + (size_t)i * D_INNER;
        const float* w_dtb  = dt_b   + (size_t)i * D_INNER;
        const float* w_Alog = A_log  + (size_t)i * D_INNER * D_STATE;
        const float* w_D    = Dp     + (size_t)i * D_INNER;

        // #2 (layer 0)
        tsplit_kernel<<<dim3(D_MODEL / 32, (2 * D_INNER) / 32), tsB>>>(
            in_proj + (size_t)i * D_MODEL * 2 * D_INNER,
            pwin_h + (size_t)i * 2 * D_INNER * D_MODEL,
            pwin_l + (size_t)i * 2 * D_INNER * D_MODEL, D_MODEL, 2 * D_INNER);
        // #3 (layer 0)
        rmsnorm_kernel<<<ROWS, 256>>>(px, w_norm, pah, pal);
        // #4 (layer 0)  <-- ncu capture target
        hmma_gemm_kernel<0><<<dim3(ROWS / 128, (2 * D_INNER) / 128), 128, GEMM_SMEM>>>(
            ROWS, 2 * D_INNER, D_MODEL, D_MODEL, D_MODEL, pah, pal,
            pwin_h + (size_t)i * 2 * D_INNER * D_MODEL,
            pwin_l + (size_t)i * 2 * D_INNER * D_MODEL,
            pxz, 2 * D_INNER, nullptr, nullptr, nullptr);

        conv_silu_kernel<<<(ROWS * D_INNER + 255) / 256, 256>>>(w_cw, w_cb);

        tsplit_kernel<<<dim3(D_INNER / 32, XP_N / 32), tsB>>>(
            x_proj + (size_t)i * D_INNER * XP_N,
            pwxp_h + (size_t)i * XP_NPAD * D_INNER,
            pwxp_l + (size_t)i * XP_NPAD * D_INNER, D_INNER, XP_N);
        hmma_gemm_kernel<3><<<dim3(ROWS / 128, 1), 128, GEMM_SMEM>>>(
            ROWS, XP_N, D_INNER, D_INNER, D_INNER, pah, pal,
            pwxp_h + (size_t)i * XP_NPAD * D_INNER,
            pwxp_l + (size_t)i * XP_NPAD * D_INNER,
            pdbl, XP_N, nullptr, pdblh, pdbll);

        tsplit_kernel<<<dim3(DT_RANK / 32, D_INNER / 32), tsB>>>(
            dt_w + (size_t)i * DT_RANK * D_INNER,
            pwdt_h + (size_t)i * D_INNER * DT_RANK,
            pwdt_l + (size_t)i * D_INNER * DT_RANK, DT_RANK, D_INNER);
        hmma_gemm_kernel<1><<<dim3(ROWS / 128, D_INNER / 128), 128, GEMM_SMEM>>>(
            ROWS, D_INNER, DT_RANK, XP_N, DT_RANK, pdblh, pdbll,
            pwdt_h + (size_t)i * D_INNER * DT_RANK,
            pwdt_l + (size_t)i * D_INNER * DT_RANK,
            pdt, D_INNER, w_dtb, nullptr, nullptr);

        scan_kernel<<<256, 256>>>(w_Alog, w_D);

        tsplit_kernel<<<dim3(D_INNER / 32, D_MODEL / 32), tsB>>>(
            out_proj + (size_t)i * D_INNER * D_MODEL,
            pwout_h + (size_t)i * D_MODEL * D_INNER,
            pwout_l + (size_t)i * D_MODEL * D_INNER, D_INNER, D_MODEL);
        hmma_gemm_kernel<2><<<dim3(ROWS / 128, D_MODEL / 128), 128, GEMM_SMEM>>>(
            ROWS, D_MODEL, D_INNER, D_INNER, D_INNER, pah, pal,
            pwout_h + (size_t)i * D_MODEL * D_INNER,
            pwout_l + (size_t)i * D_MODEL * D_INNER,
            px, D_MODEL, px, nullptr, nullptr);
    }

    rmsnorm_kernel<<<ROWS, 256>>>(px, fnorm_w, pah, pal);

    tsplit_kernel<<<dim3(D_MODEL / 32, VOCAB / 32), tsB>>>(
        head_w, phd_h, phd_l, D_MODEL, VOCAB);

    hmma_gemm_kernel<0><<<dim3(ROWS / 128, VOCAB / 128), 128, GEMM_SMEM>>>(
        ROWS, VOCAB, D_MODEL, D_MODEL, D_MODEL, pah, pal, phd_h, phd_l,
        out, VOCAB, nullptr, nullptr, nullptr);
}

// round 10
// speedup vs baseline: 1.7791x; 1.6839x over previous
#include <cuda_runtime.h>
#include <cuda_bf16.h>
#include <cstdint>

#define D_MODEL 1024
#define D_INNER 2048
#define D_STATE 16
#define DT_RANK 64
#define D_CONV  4
#define N_LAYER 4
#define VOCAB   32000
#define Bb      2
#define Ll      1024
#define ROWS    (Bb * Ll)   // 2048
#define XP_N    96
#define XP_NPAD 128

// ---------------- scratch ----------------
__device__ float g_x  [ROWS * D_MODEL];
__device__ float g_xz [ROWS * 2 * D_INNER];
__device__ float g_u  [ROWS * D_INNER];
__device__ float g_dbl[ROWS * XP_N];
__device__ float g_dt [ROWS * D_INNER];

__device__ __nv_bfloat16 g_win_h [N_LAYER * 2 * D_INNER * D_MODEL];
__device__ __nv_bfloat16 g_win_l [N_LAYER * 2 * D_INNER * D_MODEL];
__device__ __nv_bfloat16 g_wout_h[N_LAYER * D_MODEL * D_INNER];
__device__ __nv_bfloat16 g_wout_l[N_LAYER * D_MODEL * D_INNER];
__device__ __nv_bfloat16 g_wxp_h [N_LAYER * XP_NPAD * D_INNER];  // rows 96..127 zero
__device__ __nv_bfloat16 g_wxp_l [N_LAYER * XP_NPAD * D_INNER];
__device__ __nv_bfloat16 g_wdt_h [N_LAYER * D_INNER * DT_RANK];
__device__ __nv_bfloat16 g_wdt_l [N_LAYER * D_INNER * DT_RANK];
__device__ __nv_bfloat16 g_whd_h [VOCAB * D_MODEL];
__device__ __nv_bfloat16 g_whd_l [VOCAB * D_MODEL];
__device__ __nv_bfloat16 g_ah  [ROWS * D_INNER];
__device__ __nv_bfloat16 g_al  [ROWS * D_INNER];
__device__ __nv_bfloat16 g_dblh[ROWS * XP_N];
__device__ __nv_bfloat16 g_dbll[ROWS * XP_N];

// ---------------- PTX helpers ----------------
__device__ __forceinline__ uint32_t smem_u32(const void* p) {
    uint32_t a;
    asm("{ .reg .u64 t; cvta.to.shared.u64 t, %1; cvt.u32.u64 %0, t; }"
        : "=r"(a) : "l"(p));
    return a;
}
__device__ __forceinline__ void cp16(uint32_t s, const void* g) {
    asm volatile("cp.async.cg.shared.global [%0], [%1], 16;\n"
                 :: "r"(s), "l"(__cvta_generic_to_global(g)) : "memory");
}
__device__ __forceinline__ void ldm_x4(uint32_t a, uint32_t* r) {
    asm volatile("ldmatrix.sync.aligned.m8n8.x4.shared.b16 {%0,%1,%2,%3}, [%4];"
                 : "=r"(r[0]), "=r"(r[1]), "=r"(r[2]), "=r"(r[3]) : "r"(a));
}
__device__ __forceinline__ void mma16816(float* c, const uint32_t* a, const uint32_t* b) {
    asm volatile(
        "mma.sync.aligned.m16n8k16.row.col.f32.bf16.bf16.f32 "
        "{%0,%1,%2,%3},{%4,%5,%6,%7},{%8,%9},{%0,%1,%2,%3};"
        : "+f"(c[0]), "+f"(c[1]), "+f"(c[2]), "+f"(c[3])
        : "r"(a[0]), "r"(a[1]), "r"(a[2]), "r"(a[3]), "r"(b[0]), "r"(b[1]));
}
__device__ __forceinline__ void split1(float v, __nv_bfloat16* oh, __nv_bfloat16* ol) {
    __nv_bfloat16 h = __float2bfloat16(v);
    *oh = h;
    *ol = __float2bfloat16(v - __bfloat162float(h));
}

// swizzled 16B-slot offset within a 64B-row buffer: row r, chunk c (0..3)
__device__ __forceinline__ uint32_t sw_off(int r, int c) {
    return (uint32_t)r * 64u + (uint32_t)((c ^ ((r >> 1) & 3)) << 4);
}

// ---------------- HMMA GEMM ----------------
// C[M,N] = A[M,K]*Bt[N,K]^T; bf16 hi/lo 3-term split. CTA 128x128, 128 thr
// (2x2 warps, 64x64 warp tile), BK=32, 3-stage cp.async, swizzled smem,
// 2 CTAs/SM. EPI 0 plain, 1 softplus(+bias[col]), 2 +aux[r,c], 3 +split Ch/Cl
#define BUFS   8192
#define STAGE  (4 * BUFS)
#define NSTG   3
#define GEMM_SMEM (NSTG * STAGE)      // 98304

template <int EPI>
__global__ __launch_bounds__(128)
void hmma_gemm_kernel(int M, int N, int K, int lda, int ldb,
                      const __nv_bfloat16* __restrict__ Ah,
                      const __nv_bfloat16* __restrict__ Al,
                      const __nv_bfloat16* __restrict__ Bh,
                      const __nv_bfloat16* __restrict__ Bl,
                      float* __restrict__ C, int ldc,
                      const float* __restrict__ aux,
                      __nv_bfloat16* __restrict__ Ch,
                      __nv_bfloat16* __restrict__ Cl) {
    extern __shared__ char smem[];
    const uint32_t sb = smem_u32(smem);
    const int tid  = threadIdx.x;
    const int lane = tid & 31;
    const int w    = tid >> 5;
    const int wm   = w >> 1;
    const int wn   = w & 1;
    const int rowA = blockIdx.x * 128;
    const int colC = blockIdx.y * 128;

    const int kiters = K >> 5;

    auto load_stage = [&](int it) {
        const uint32_t st = sb + (uint32_t)(it % NSTG) * STAGE;
        const int k0 = it << 5;
        #pragma unroll
        for (int t = 0; t < 4; t++) {
            int idx = tid + t * 128;
            int r = idx >> 2, c = idx & 3;
            uint32_t so = sw_off(r, c);
            const size_t ga = (size_t)(rowA + r) * lda + k0 + c * 8;
            const size_t gb = (size_t)(colC + r) * ldb + k0 + c * 8;
            cp16(st +            so, Ah + ga);
            cp16(st + BUFS     + so, Al + ga);
            cp16(st + 2 * BUFS + so, Bh + gb);
            cp16(st + 3 * BUFS + so, Bl + gb);
        }
        asm volatile("cp.async.commit_group;" ::: "memory");
    };

    float acc[4][8][4];
    #pragma unroll
    for (int m = 0; m < 4; m++)
        #pragma unroll
        for (int n = 0; n < 8; n++)
            #pragma unroll
            for (int e = 0; e < 4; e++) acc[m][n][e] = 0.f;

    load_stage(0);
    if (kiters > 1) load_stage(1);

    const int lr  = lane & 15;
    const int lc  = lane >> 4;

    for (int i = 0; i < kiters; i++) {
        if (i + 1 < kiters) asm volatile("cp.async.wait_group 1;" ::: "memory");
        else                asm volatile("cp.async.wait_group 0;" ::: "memory");
        __syncthreads();
        if (i + 2 < kiters) load_stage(i + 2);

        const uint32_t st = sb + (uint32_t)(i % NSTG) * STAGE;
        #pragma unroll
        for (int kk = 0; kk < 2; kk++) {
            const int cbase = kk * 2 + lc;
            uint32_t ah[4][4], al[4][4], bh[8][2], bl[8][2];
            #pragma unroll
            for (int m = 0; m < 4; m++) {
                int r = wm * 64 + m * 16 + lr;
                uint32_t adr = st + sw_off(r, cbase);
                ldm_x4(adr, ah[m]);
                ldm_x4(adr + BUFS, al[m]);
            }
            #pragma unroll
            for (int n2 = 0; n2 < 4; n2++) {
                int r = wn * 64 + n2 * 16 + lr;
                uint32_t adr = st + 2 * BUFS + sw_off(r, cbase);
                uint32_t r4[4];
                ldm_x4(adr, r4);
                bh[2*n2][0] = r4[0]; bh[2*n2+1][0] = r4[1];
                bh[2*n2][1] = r4[2]; bh[2*n2+1][1] = r4[3];
                ldm_x4(adr + BUFS, r4);
                bl[2*n2][0] = r4[0]; bl[2*n2+1][0] = r4[1];
                bl[2*n2][1] = r4[2]; bl[2*n2+1][1] = r4[3];
            }
            #pragma unroll
            for (int m = 0; m < 4; m++)
                #pragma unroll
                for (int n = 0; n < 8; n++)
                    mma16816(acc[m][n], ah[m], bh[n]);
            #pragma unroll
            for (int m = 0; m < 4; m++)
                #pragma unroll
                for (int n = 0; n < 8; n++)
                    mma16816(acc[m][n], ah[m], bl[n]);
            #pragma unroll
            for (int m = 0; m < 4; m++)
                #pragma unroll
                for (int n = 0; n < 8; n++)
                    mma16816(acc[m][n], al[m], bh[n]);
        }
        // no trailing sync: next iteration's leading __syncthreads protects
        // buffer (i+2)%3 == (i-1)%3 reuse.
    }

    const int er = lane >> 2;
    const int ec = (lane & 3) * 2;
    #pragma unroll
    for (int m = 0; m < 4; m++) {
        const int grow = rowA + wm * 64 + m * 16 + er;
        #pragma unroll
        for (int n = 0; n < 8; n++) {
            const int gcol = colC + wn * 64 + n * 8 + ec;
            if (gcol >= N) continue;
            float2 v0 = make_float2(acc[m][n][0], acc[m][n][1]);
            float2 v1 = make_float2(acc[m][n][2], acc[m][n][3]);
            if (EPI == 1) {
                float b0 = aux[gcol], b1 = aux[gcol + 1];
                v0.x += b0; v0.y += b1;
                v1.x += b0; v1.y += b1;
                v0.x = (v0.x > 20.f) ? v0.x : log1pf(__expf(v0.x));
                v0.y = (v0.y > 20.f) ? v0.y : log1pf(__expf(v0.y));
                v1.x = (v1.x > 20.f) ? v1.x : log1pf(__expf(v1.x));
                v1.y = (v1.y > 20.f) ? v1.y : log1pf(__expf(v1.y));
            } else if (EPI == 2) {
                float2 a0 = *reinterpret_cast<const float2*>(
                    aux + (size_t)grow * ldc + gcol);
                float2 a1 = *reinterpret_cast<const float2*>(
                    aux + (size_t)(grow + 8) * ldc + gcol);
                v0.x += a0.x; v0.y += a0.y;
                v1.x += a1.x; v1.y += a1.y;
            }
            *reinterpret_cast<float2*>(C + (size_t)grow * ldc + gcol) = v0;
            *reinterpret_cast<float2*>(C + (size_t)(grow + 8) * ldc + gcol) = v1;
            if (EPI == 3) {
                __nv_bfloat16 h0, l0, h1, l1;
                split1(v0.x, &h0, &l0); split1(v0.y, &h1, &l1);
                *reinterpret_cast<__nv_bfloat162*>(Ch + (size_t)grow * ldc + gcol) =
                    __nv_bfloat162(h0, h1);
                *reinterpret_cast<__nv_bfloat162*>(Cl + (size_t)grow * ldc + gcol) =
                    __nv_bfloat162(l0, l1);
                split1(v1.x, &h0, &l0); split1(v1.y, &h1, &l1);
                *reinterpret_cast<__nv_bfloat162*>(Ch + (size_t)(grow + 8) * ldc + gcol) =
                    __nv_bfloat162(h0, h1);
                *reinterpret_cast<__nv_bfloat162*>(Cl + (size_t)(grow + 8) * ldc + gcol) =
                    __nv_bfloat162(l0, l1);
            }
        }
    }
}

// ---------------- transpose + bf16 split: in[R,C] -> hi/lo [C,R] ----------
// block (16,16); float2 loads, bf162 stores.
__global__ void tsplit_kernel(const float* __restrict__ in,
                              __nv_bfloat16* __restrict__ oh,
                              __nv_bfloat16* __restrict__ ol, int R, int Ccols) {
    __shared__ float t[32][33];
    int rb = blockIdx.x * 32, cb = blockIdx.y * 32;
    int tx = threadIdx.x, ty = threadIdx.y;
    #pragma unroll
    for (int j = 0; j < 2; j++) {
        int r = ty + 16 * j;
        float2 v = *reinterpret_cast<const float2*>(
            in + (size_t)(rb + r) * Ccols + cb + 2 * tx);
        t[r][2 * tx]     = v.x;
        t[r][2 * tx + 1] = v.y;
    }
    __syncthreads();
    #pragma unroll
    for (int j = 0; j < 2; j++) {
        int c = ty + 16 * j;
        float a = t[2 * tx][c];
        float b = t[2 * tx + 1][c];
        __nv_bfloat16 ha, la, hb, lb;
        split1(a, &ha, &la);
        split1(b, &hb, &lb);
        size_t o = (size_t)(cb + c) * R + rb + 2 * tx;
        *reinterpret_cast<__nv_bfloat162*>(oh + o) = __nv_bfloat162(ha, hb);
        *reinterpret_cast<__nv_bfloat162*>(ol + o) = __nv_bfloat162(la, lb);
    }
}

// ---------------- embedding ----------------
__global__ void embed_kernel(const int* __restrict__ tokens,
                             const float* __restrict__ emb) {
    int idx = blockIdx.x * blockDim.x + threadIdx.x;
    if (idx >= ROWS * D_MODEL) return;
    int row = idx / D_MODEL;
    int c   = idx % D_MODEL;
    g_x[idx] = emb[tokens[row] * D_MODEL + c];
}

// ---------------- rmsnorm -> bf16 hi/lo ----------------
__global__ void rmsnorm_kernel(const float* __restrict__ in,
                               const float* __restrict__ w,
                               __nv_bfloat16* __restrict__ oh,
                               __nv_bfloat16* __restrict__ ol) {
    __shared__ float red[8];
    int row = blockIdx.x;
    const float4* x4 = reinterpret_cast<const float4*>(in + (size_t)row * D_MODEL);
    float4 v = x4[threadIdx.x];
    float s = v.x * v.x + v.y * v.y + v.z * v.z + v.w * v.w;
    #pragma unroll
    for (int o = 16; o > 0; o >>= 1) s += __shfl_xor_sync(0xffffffffu, s, o);
    if ((threadIdx.x & 31) == 0) red[threadIdx.x >> 5] = s;
    __syncthreads();
    if (threadIdx.x < 8) {
        float t = red[threadIdx.x];
        #pragma unroll
        for (int o = 4; o > 0; o >>= 1) t += __shfl_xor_sync(0xffu, t, o);
        if (threadIdx.x == 0) red[0] = t;
    }
    __syncthreads();
    float rs = rsqrtf(red[0] * (1.0f / D_MODEL) + 1e-5f);
    const float4* w4 = reinterpret_cast<const float4*>(w);
    float4 wv = w4[threadIdx.x];
    size_t base = (size_t)row * D_MODEL + threadIdx.x * 4;
    split1(v.x * rs * wv.x, oh + base + 0, ol + base + 0);
    split1(v.y * rs * wv.y, oh + base + 1, ol + base + 1);
    split1(v.z * rs * wv.z, oh + base + 2, ol + base + 2);
    split1(v.w * rs * wv.w, oh + base + 3, ol + base + 3);
}

// ---------------- depthwise causal conv1d + silu ----------------
__global__ void conv_silu_kernel(const float* __restrict__ conv_w,
                                 const float* __restrict__ conv_b) {
    int idx = blockIdx.x * blockDim.x + threadIdx.x;
    if (idx >= ROWS * D_INNER) return;
    int d = idx % D_INNER;
    int row = idx / D_INNER;
    int l = row % Ll;
    int rowbase = row - l;
    float acc = conv_b[d];
    #pragma unroll
    for (int k = 0; k < D_CONV; k++) {
        int ll = l - (D_CONV - 1) + k;
        if (ll >= 0)
            acc = fmaf(conv_w[d * D_CONV + k],
                       g_xz[(size_t)(rowbase + ll) * (2 * D_INNER) + d], acc);
    }
    float s = acc / (1.f + __expf(-acc));
    g_u[idx] = s;
    split1(s, g_ah + idx, g_al + idx);
}

// ---------------- selective scan v2: smem-staged, double-buffered ---------
// 128 blocks x 512 threads; 32 channels/block (one b each); 128-step chunks.
#define TT 128
#define SCAN_STF (TT * 128)                  // floats per stage
#define SCAN_SMEM (2 * SCAN_STF * 4)         // 131072 B

__global__ __launch_bounds__(512)
void scan2_kernel(const float* __restrict__ A_log,
                  const float* __restrict__ Dp) {
    extern __shared__ float S[];
    const int tid = threadIdx.x;
    const int b = blockIdx.x >> 6;
    const int dbase = (blockIdx.x & 63) * 32;
    const int rowbase = b * Ll;

    const int w = tid >> 5, lane = tid & 31;
    const int n = lane & 15;
    const int dloc = w * 2 + (lane >> 4);
    const int d = dbase + dloc;

    const float An = -__expf(A_log[d * D_STATE + n]);
    const float Dd = Dp[d];
    float h = 0.f;

    auto load_chunk = [&](int c) {
        float* st = S + (c & 1) * SCAN_STF;
        const int t0 = c * TT;
        // dt, u, z : TT rows x 32 floats each
        for (int idx = tid; idx < TT * 8; idx += 512) {
            int tr = idx >> 3, c4 = idx & 7;
            size_t grow = (size_t)(rowbase + t0 + tr);
            cp16(smem_u32(st + tr * 32 + c4 * 4),
                 g_dt + grow * D_INNER + dbase + c4 * 4);
            cp16(smem_u32(st + TT * 32 + tr * 32 + c4 * 4),
                 g_u + grow * D_INNER + dbase + c4 * 4);
            cp16(smem_u32(st + TT * 64 + tr * 32 + c4 * 4),
                 g_xz + grow * 2 * D_INNER + D_INNER + dbase + c4 * 4);
        }
        // B, C : TT rows x 16 floats each
        for (int idx = tid; idx < TT * 4; idx += 512) {
            int tr = idx >> 2, c4 = idx & 3;
            size_t grow = (size_t)(rowbase + t0 + tr);
            cp16(smem_u32(st + TT * 96 + tr * 16 + c4 * 4),
                 g_dbl + grow * XP_N + DT_RANK + c4 * 4);
            cp16(smem_u32(st + TT * 112 + tr * 16 + c4 * 4),
                 g_dbl + grow * XP_N + DT_RANK + D_STATE + c4 * 4);
        }
        asm volatile("cp.async.commit_group;" ::: "memory");
    };

    load_chunk(0);
    load_chunk(1);

    const int NC = Ll / TT;   // 8
    for (int c = 0; c < NC; c++) {
        if (c + 1 < NC) asm volatile("cp.async.wait_group 1;" ::: "memory");
        else            asm volatile("cp.async.wait_group 0;" ::: "memory");
        __syncthreads();
        float* st  = S + (c & 1) * SCAN_STF;
        float* sdt = st;
        float* su  = st + TT * 32;
        float* sz  = st + TT * 64;
        float* sB  = st + TT * 96;
        float* sC  = st + TT * 112;
        #pragma unroll 4
        for (int t = 0; t < TT; t++) {
            float dt_v = sdt[t * 32 + dloc];
            float u_v  = su [t * 32 + dloc];
            float Bn   = sB [t * 16 + n];
            float Cn   = sC [t * 16 + n];
            h = fmaf(__expf(dt_v * An), h, dt_v * Bn * u_v);
            float p = h * Cn;
            #pragma unroll
            for (int o = 8; o > 0; o >>= 1)
                p += __shfl_xor_sync(0xffffffffu, p, o);
            if (n == 0) {
                float zv = sz[t * 32 + dloc];
                float yv = (p + u_v * Dd) * (zv / (1.f + __expf(-zv)));
                size_t o = (size_t)(rowbase + c * TT + t) * D_INNER + d;
                split1(yv, g_ah + o, g_al + o);
            }
        }
        __syncthreads();
        if (c + 2 < NC) load_chunk(c + 2);
    }
}

// ---------------- launch ----------------
extern "C" void kernel_launch(void* const* d_in, const int* in_sizes, int n_in,
                              void* d_out, int out_size) {
    const int*   tokens    = (const int*)  d_in[0];
    const float* embedding = (const float*)d_in[1];
    const float* norm_w    = (const float*)d_in[2];
    const float* in_proj   = (const float*)d_in[3];
    const float* conv_w    = (const float*)d_in[4];
    const float* conv_b    = (const float*)d_in[5];
    const float* x_proj    = (const float*)d_in[6];
    const float* dt_w      = (const float*)d_in[7];
    const float* dt_b      = (const float*)d_in[8];
    const float* A_log     = (const float*)d_in[9];
    const float* Dp        = (const float*)d_in[10];
    const float* out_proj  = (const float*)d_in[11];
    const float* fnorm_w   = (const float*)d_in[12];
    const float* head_w    = (const float*)d_in[13];
    float* out = (float*)d_out;

    float *px, *pxz, *pu, *pdbl, *pdt;
    cudaGetSymbolAddress((void**)&px,  g_x);
    cudaGetSymbolAddress((void**)&pxz, g_xz);
    cudaGetSymbolAddress((void**)&pu,  g_u);
    cudaGetSymbolAddress((void**)&pdbl,g_dbl);
    cudaGetSymbolAddress((void**)&pdt, g_dt);

    __nv_bfloat16 *pwin_h, *pwin_l, *pwout_h, *pwout_l, *pwxp_h, *pwxp_l,
                  *pwdt_h, *pwdt_l, *phd_h, *phd_l, *pah, *pal, *pdblh, *pdbll;
    cudaGetSymbolAddress((void**)&pwin_h,  g_win_h);
    cudaGetSymbolAddress((void**)&pwin_l,  g_win_l);
    cudaGetSymbolAddress((void**)&pwout_h, g_wout_h);
    cudaGetSymbolAddress((void**)&pwout_l, g_wout_l);
    cudaGetSymbolAddress((void**)&pwxp_h,  g_wxp_h);
    cudaGetSymbolAddress((void**)&pwxp_l,  g_wxp_l);
    cudaGetSymbolAddress((void**)&pwdt_h,  g_wdt_h);
    cudaGetSymbolAddress((void**)&pwdt_l,  g_wdt_l);
    cudaGetSymbolAddress((void**)&phd_h,   g_whd_h);
    cudaGetSymbolAddress((void**)&phd_l,   g_whd_l);
    cudaGetSymbolAddress((void**)&pah,     g_ah);
    cudaGetSymbolAddress((void**)&pal,     g_al);
    cudaGetSymbolAddress((void**)&pdblh,   g_dblh);
    cudaGetSymbolAddress((void**)&pdbll,   g_dbll);

    cudaFuncSetAttribute(hmma_gemm_kernel<0>,
                         cudaFuncAttributeMaxDynamicSharedMemorySize, GEMM_SMEM);
    cudaFuncSetAttribute(hmma_gemm_kernel<1>,
                         cudaFuncAttributeMaxDynamicSharedMemorySize, GEMM_SMEM);
    cudaFuncSetAttribute(hmma_gemm_kernel<2>,
                         cudaFuncAttributeMaxDynamicSharedMemorySize, GEMM_SMEM);
    cudaFuncSetAttribute(hmma_gemm_kernel<3>,
                         cudaFuncAttributeMaxDynamicSharedMemorySize, GEMM_SMEM);
    cudaFuncSetAttribute(scan2_kernel,
                         cudaFuncAttributeMaxDynamicSharedMemorySize, SCAN_SMEM);

    dim3 tsB(16, 16);

    // #1
    embed_kernel<<<(ROWS * D_MODEL + 255) / 256, 256>>>(tokens, embedding);

    for (int i = 0; i < N_LAYER; i++) {
        const float* w_norm = norm_w + (size_t)i * D_MODEL;
        const float* w_cw   = conv_w + (size_t)i * D_INNER * D_CONV;
        const float* w_cb   = conv_b + (size_t)i * D_INNER;
        const float* w_dtb  = dt_b   + (size_t)i * D_INNER;
        const float* w_Alog = A_log  + (size_t)i * D_INNER * D_STATE;
        const float* w_D    = Dp     + (size_t)i * D_INNER;

        // #2 (layer 0)
        tsplit_kernel<<<dim3(D_MODEL / 32, (2 * D_INNER) / 32), tsB>>>(
            in_proj + (size_t)i * D_MODEL * 2 * D_INNER,
            pwin_h + (size_t)i * 2 * D_INNER * D_MODEL,
            pwin_l + (size_t)i * 2 * D_INNER * D_MODEL, D_MODEL, 2 * D_INNER);
        // #3 (layer 0)
        rmsnorm_kernel<<<ROWS, 256>>>(px, w_norm, pah, pal);
        // #4 (layer 0)  <-- ncu capture target
        hmma_gemm_kernel<0><<<dim3(ROWS / 128, (2 * D_INNER) / 128), 128, GEMM_SMEM>>>(
            ROWS, 2 * D_INNER, D_MODEL, D_MODEL, D_MODEL, pah, pal,
            pwin_h + (size_t)i * 2 * D_INNER * D_MODEL,
            pwin_l + (size_t)i * 2 * D_INNER * D_MODEL,
            pxz, 2 * D_INNER, nullptr, nullptr, nullptr);

        conv_silu_kernel<<<(ROWS * D_INNER + 255) / 256, 256>>>(w_cw, w_cb);

        tsplit_kernel<<<dim3(D_INNER / 32, XP_N / 32), tsB>>>(
            x_proj + (size_t)i * D_INNER * XP_N,
            pwxp_h + (size_t)i * XP_NPAD * D_INNER,
            pwxp_l + (size_t)i * XP_NPAD * D_INNER, D_INNER, XP_N);
        hmma_gemm_kernel<3><<<dim3(ROWS / 128, 1), 128, GEMM_SMEM>>>(
            ROWS, XP_N, D_INNER, D_INNER, D_INNER, pah, pal,
            pwxp_h + (size_t)i * XP_NPAD * D_INNER,
            pwxp_l + (size_t)i * XP_NPAD * D_INNER,
            pdbl, XP_N, nullptr, pdblh, pdbll);

        tsplit_kernel<<<dim3(DT_RANK / 32, D_INNER / 32), tsB>>>(
            dt_w + (size_t)i * DT_RANK * D_INNER,
            pwdt_h + (size_t)i * D_INNER * DT_RANK,
            pwdt_l + (size_t)i * D_INNER * DT_RANK, DT_RANK, D_INNER);
        hmma_gemm_kernel<1><<<dim3(ROWS / 128, D_INNER / 128), 128, GEMM_SMEM>>>(
            ROWS, D_INNER, DT_RANK, XP_N, DT_RANK, pdblh, pdbll,
            pwdt_h + (size_t)i * D_INNER * DT_RANK,
            pwdt_l + (size_t)i * D_INNER * DT_RANK,
            pdt, D_INNER, w_dtb, nullptr, nullptr);

        scan2_kernel<<<128, 512, SCAN_SMEM>>>(w_Alog, w_D);

        tsplit_kernel<<<dim3(D_INNER / 32, D_MODEL / 32), tsB>>>(
            out_proj + (size_t)i * D_INNER * D_MODEL,
            pwout_h + (size_t)i * D_MODEL * D_INNER,
            pwout_l + (size_t)i * D_MODEL * D_INNER, D_INNER, D_MODEL);
        hmma_gemm_kernel<2><<<dim3(ROWS / 128, D_MODEL / 128), 128, GEMM_SMEM>>>(
            ROWS, D_MODEL, D_INNER, D_INNER, D_INNER, pah, pal,
            pwout_h + (size_t)i * D_MODEL * D_INNER,
            pwout_l + (size_t)i * D_MODEL * D_INNER,
            px, D_MODEL, px, nullptr, nullptr);
    }

    rmsnorm_kernel<<<ROWS, 256>>>(px, fnorm_w, pah, pal);

    tsplit_kernel<<<dim3(D_MODEL / 32, VOCAB / 32), tsB>>>(
        head_w, phd_h, phd_l, D_MODEL, VOCAB);

    hmma_gemm_kernel<0><<<dim3(ROWS / 128, VOCAB / 128), 128, GEMM_SMEM>>>(
        ROWS, VOCAB, D_MODEL, D_MODEL, D_MODEL, pah, pal, phd_h, phd_l,
        out, VOCAB, nullptr, nullptr, nullptr);
}